// round 3
// baseline (speedup 1.0000x reference)
#include <cuda_runtime.h>

// Problem constants: N=1, C=64, H=W=80
#define LL    6400      // H*W
#define WW    80
#define NTILE 50        // 6400 / 128
#define NEGV  (-1e9f)

// Scratch (static __device__ — no allocations allowed)
__device__ float g_rowv[LL * NTILE];   // per-(row, coltile) partial max
__device__ int   g_rowj[LL * NTILE];   // per-(row, coltile) partial argmax
__device__ float g_colp[LL * NTILE];   // per-(col, rowtile) partial max
__device__ float g_colmax[LL];         // final column max

// Packed fp32x2 FMA (Blackwell): d = a*b + d per 32-bit lane.
// IEEE-identical per lane to scalar fmaf -> downstream equality logic unchanged.
__device__ __forceinline__ void ffma2(unsigned long long& d,
                                      unsigned long long a,
                                      unsigned long long b)
{
    asm("fma.rn.f32x2 %0, %1, %2, %0;" : "+l"(d) : "l"(a), "l"(b));
}

// ---------------------------------------------------------------------------
// Kernel 1: fused conf tile + reductions.
// conf[i,j] = dot_c(A[c,i], B[c,j]) * 0.15625, masked to NEGV where saliency
// invalid. Each (i,j) computed once; reduced into row-(max,argmax) and col-max
// partials. conf never stored.
//
// Mainloop: acc2[x2][y] packs rows (2*x2, 2*x2+1). B is stored PRE-DUPLICATED
// in smem as (b,b) pairs so no broadcast MOVs are needed; layout is
// interleaved in 16B units u = s*16 + ty so the 4 LDS.128/thread/k are
// conflict-free (ty-stride = 16B within a phase).
// ---------------------------------------------------------------------------
__global__ __launch_bounds__(256, 2)
void conf_kernel(const float* __restrict__ A, const float* __restrict__ B,
                 const float* __restrict__ saV, const float* __restrict__ saI)
{
    __shared__ float As[32][128];     // 16 KB ; aliased as colsm after mainloop
    __shared__ float Bs2[32][256];    // 32 KB ; duplicated pairs, interleaved

    const int ct = blockIdx.x;          // column tile
    const int rt = blockIdx.y;          // row tile
    const int i0 = rt * 128;
    const int j0 = ct * 128;
    const int tid = threadIdx.x;
    const int tx = tid >> 4;            // 0..15 -> 8 rows each
    const int ty = tid & 15;            // 0..15 -> 8 cols each

    unsigned long long acc2[4][8];      // [x-pair][y]; low half = even row
#pragma unroll
    for (int x2 = 0; x2 < 4; x2++)
#pragma unroll
        for (int y = 0; y < 8; y++) acc2[x2][y] = 0ull;

    // K=64 in two 32-deep phases
    for (int kb = 0; kb < 64; kb += 32) {
#pragma unroll
        for (int s = 0; s < 4; s++) {
            int f4 = tid + s * 256;          // 1024 float4 per tile
            int c  = f4 >> 5;                // 0..31
            int j4 = (f4 & 31) << 2;         // 0..124 step 4
            *(float4*)&As[c][j4] = *(const float4*)&A[(kb + c) * LL + i0 + j4];
            // B: duplicate each value into an 8-byte pair, interleaved layout.
            // unit u = (y>>1)*16 + (j>>3) holds (dup b[j_even], dup b[j_odd]).
            float4 bv = *(const float4*)&B[(kb + c) * LL + j0 + j4];
            int ty_r = j4 >> 3;
            int y0   = j4 & 7;               // 0 or 4
            int u0   = (y0 >> 1) * 16 + ty_r;
            int u1   = (y0 / 2 + 1) * 16 + ty_r;
            *(float4*)&Bs2[c][u0 * 4] = make_float4(bv.x, bv.x, bv.y, bv.y);
            *(float4*)&Bs2[c][u1 * 4] = make_float4(bv.z, bv.z, bv.w, bv.w);
        }
        __syncthreads();

#pragma unroll 8
        for (int k = 0; k < 32; k++) {
            __align__(16) unsigned long long a2[4];   // row pairs
            *(float4*)&a2[0] = *(float4*)&As[k][tx * 8];
            *(float4*)&a2[2] = *(float4*)&As[k][tx * 8 + 4];
            __align__(16) unsigned long long bb[8];   // duplicated col values
#pragma unroll
            for (int s = 0; s < 4; s++)
                *(float4*)&bb[2 * s] = *(float4*)&Bs2[k][(s * 16 + ty) << 2];
#pragma unroll
            for (int y = 0; y < 8; y++)
#pragma unroll
                for (int x2 = 0; x2 < 4; x2++)
                    ffma2(acc2[x2][y], a2[x2], bb[y]);
        }
        __syncthreads();
    }

    // Unpack packed accumulators -> acc[x][y] (low half is even row)
    float acc[8][8];
#pragma unroll
    for (int x2 = 0; x2 < 4; x2++)
#pragma unroll
        for (int y = 0; y < 8; y++) {
            float2 f = *(float2*)&acc2[x2][y];
            acc[2 * x2][y]     = f.x;
            acc[2 * x2 + 1][y] = f.y;
        }

    // Saliency validity masks
    bool vr[8], vc[8];
#pragma unroll
    for (int x = 0; x < 8; x++) vr[x] = saV[i0 + tx * 8 + x] > 0.f;
#pragma unroll
    for (int y = 0; y < 8; y++) vc[y] = saI[j0 + ty * 8 + y] > 0.f;

    // Scale + mask in place (this is THE conf value; used for both reductions)
#pragma unroll
    for (int x = 0; x < 8; x++)
#pragma unroll
        for (int y = 0; y < 8; y++)
            acc[x][y] = (vr[x] && vc[y]) ? acc[x][y] * 0.15625f : NEGV;

    // -------- column partial max (colsm aliases As; safe after the sync) --------
    float (*colsm)[128] = (float (*)[128])As;
#pragma unroll
    for (int y = 0; y < 8; y++) {
        float m = acc[0][y];
#pragma unroll
        for (int x = 1; x < 8; x++) m = fmaxf(m, acc[x][y]);
        colsm[tx][ty * 8 + y] = m;
    }

    // -------- row (max, first-argmax): local scan + shfl over 16 lanes --------
#pragma unroll
    for (int x = 0; x < 8; x++) {
        float v = acc[x][0];
        int   j = j0 + ty * 8;
#pragma unroll
        for (int y = 1; y < 8; y++) {
            if (acc[x][y] > v) { v = acc[x][y]; j = j0 + ty * 8 + y; }
        }
        // reduce across 16 ty-lanes (lane = (tx&1)*16 + ty). ties -> min j.
#pragma unroll
        for (int d = 1; d < 16; d <<= 1) {
            float ov = __shfl_xor_sync(0xffffffffu, v, d);
            int   oj = __shfl_xor_sync(0xffffffffu, j, d);
            if (ov > v || (ov == v && oj < j)) { v = ov; j = oj; }
        }
        if (ty == 0) {
            int i = i0 + tx * 8 + x;
            g_rowv[i * NTILE + ct] = v;
            g_rowj[i * NTILE + ct] = j;
        }
    }

    __syncthreads();
    // finish column reduction across the 16 tx-groups
    if (tid < 128) {
        float m = colsm[0][tid];
#pragma unroll
        for (int t = 1; t < 16; t++) m = fmaxf(m, colsm[t][tid]);
        g_colp[(j0 + tid) * NTILE + rt] = m;
    }
}

// ---------------------------------------------------------------------------
// Kernel 2: column-partial reduce (blocks 0..24) + bilinear upsample
// 80x80 -> 640x640 align_corners (blocks 25..1624). Independent work merged
// to overlap and cut launch tail.
// ---------------------------------------------------------------------------
__global__ void colmax_upsample_kernel(const float* __restrict__ in,
                                       float* __restrict__ out)
{
    if (blockIdx.x < 25) {
        int j = blockIdx.x * 256 + threadIdx.x;
        float m = g_colp[j * NTILE];
#pragma unroll 5
        for (int t = 1; t < NTILE; t++) m = fmaxf(m, g_colp[j * NTILE + t]);
        g_colmax[j] = m;
        return;
    }
    int o = (blockIdx.x - 25) * 256 + threadIdx.x;
    int oy = o / 640, ox = o % 640;
    const float step = 79.0f / 639.0f;
    float ysf = oy * step;
    float xsf = ox * step;
    int y0 = (int)ysf;
    int x0 = (int)xsf;
    int y1 = min(y0 + 1, WW - 1);
    int x1 = min(x0 + 1, WW - 1);
    float wy = ysf - (float)y0;
    float wx = xsf - (float)x0;
    float v00 = in[y0 * WW + x0], v01 = in[y0 * WW + x1];
    float v10 = in[y1 * WW + x0], v11 = in[y1 * WW + x1];
    float r0 = v00 * (1.f - wy) + v10 * wy;   // interp along H first (matches reference)
    float r1 = v01 * (1.f - wy) + v11 * wy;
    out[38400 + o] = r0 * (1.f - wx) + r1 * wx;
}

// ---------------------------------------------------------------------------
// Kernel 3: per-row finalize — mutual-NN test + outputs
// out layout (flattened tuple, float32):
//   [0      : 12800)  mkpts0  [L,2]
//   [12800  : 25600)  mkpts1  [1,L,2]
//   [25600  : 32000)  mask_v  [1,L]
//   [32000  : 38400)  score   [1,L]
//   [38400  : 448000) sa_ir_up [1,1,640,640]
// ---------------------------------------------------------------------------
__global__ void finalize_kernel(float* __restrict__ out)
{
    int i = blockIdx.x * 256 + threadIdx.x;
    if (i >= LL) return;

    float best = g_rowv[i * NTILE];
    int   bj   = g_rowj[i * NTILE];
#pragma unroll 5
    for (int t = 1; t < NTILE; t++) {
        float v = g_rowv[i * NTILE + t];
        if (v > best) { best = v; bj = g_rowj[i * NTILE + t]; }  // strict > keeps first occurrence
    }

    // mutual nearest neighbor: row max must also be its column's max, and > 0
    float mv = (best > 0.f && best == g_colmax[bj]) ? 1.f : 0.f;
    int   aj = (mv > 0.f) ? bj : 0;   // jnp.argmax of all-zero mask row -> 0

    out[2 * i]     = (float)((i % WW) * 8);
    out[2 * i + 1] = (float)((i / WW) * 8);
    out[12800 + 2 * i]     = (float)((aj % WW) * 8);
    out[12800 + 2 * i + 1] = (float)((aj / WW) * 8);
    out[25600 + i] = mv;
    out[32000 + i] = (mv > 0.f) ? best : 0.f;
}

// ---------------------------------------------------------------------------
extern "C" void kernel_launch(void* const* d_in, const int* in_sizes, int n_in,
                              void* d_out, int out_size)
{
    const float* A   = (const float*)d_in[0];   // feat_reg_vi [1,64,80,80]
    const float* B   = (const float*)d_in[1];   // feat_reg_ir [1,64,80,80]
    const float* saV = (const float*)d_in[2];   // feat_sa_vi  [1,1,80,80]
    const float* saI = (const float*)d_in[3];   // feat_sa_ir  [1,1,80,80]
    float* out = (float*)d_out;

    dim3 grid(NTILE, NTILE);
    conf_kernel<<<grid, 256>>>(A, B, saV, saI);
    colmax_upsample_kernel<<<1625, 256>>>(saI, out);
    finalize_kernel<<<25, 256>>>(out);
}

// round 4
// speedup vs baseline: 1.1581x; 1.1581x over previous
#include <cuda_runtime.h>

// Problem constants: N=1, C=64, H=W=80
#define LL    6400      // H*W
#define WW    80
#define NTILE 50        // 6400 / 128
#define NEGV  (-1e9f)

// Scratch (static __device__ — no allocations allowed). Transposed layouts:
__device__ float g_rowv[NTILE * LL];   // [coltile][row] partial max
__device__ int   g_rowj[NTILE * LL];   // [coltile][row] partial argmax
__device__ float g_colp[NTILE * LL];   // [rowtile][col] partial max
__device__ float g_colmax[LL];         // final column max

// Packed fp32x2 FMA (Blackwell): d = a*b + d per 32-bit lane.
// IEEE-identical per lane to scalar fmaf -> equality logic unchanged.
__device__ __forceinline__ void ffma2(unsigned long long& d,
                                      unsigned long long a,
                                      unsigned long long b)
{
    asm("fma.rn.f32x2 %0, %1, %2, %0;" : "+l"(d) : "l"(a), "l"(b));
}

// Broadcast one fp32 into both halves of a 64-bit packed register.
__device__ __forceinline__ unsigned long long bcast2(float v)
{
    unsigned long long r;
    asm("mov.b64 %0, {%1, %1};" : "=l"(r) : "r"(__float_as_uint(v)));
    return r;
}

// ---------------------------------------------------------------------------
// Kernel 1: fused conf tile + reductions. 128x128 tile, 128 threads,
// 16x8 micro-tile => LDS traffic (96 B/thread/k) sits at 75% of the FFMA2
// demand, so the fma pipe is the sole binding resource.
//   A: natural layout; per-k loads are 16-way-broadcast LDS.128 (conflict-free)
//   B: interleaved 16B units u=(g&1)*16+(g>>1) so the two per-k LDS.128 are
//      stride-16B across the 16 ty lanes (conflict-free, proven in R3).
// ---------------------------------------------------------------------------
__global__ __launch_bounds__(128, 2)
void conf_kernel(const float* __restrict__ A, const float* __restrict__ B,
                 const float* __restrict__ saV, const float* __restrict__ saI)
{
    __shared__ float As[32][128];     // 16 KB (aliased as colsm in epilogue)
    __shared__ float Bs[32][128];     // 16 KB, interleaved units

    const int ct = blockIdx.x;          // column tile
    const int rt = blockIdx.y;          // row tile
    const int i0 = rt * 128;
    const int j0 = ct * 128;
    const int tid = threadIdx.x;        // 0..127
    const int tx = tid >> 4;            // 0..7  -> 16 rows each
    const int ty = tid & 15;            // 0..15 -> 8 cols each

    unsigned long long acc2[8][8];      // [row-pair][col]; low half = even row
#pragma unroll
    for (int x2 = 0; x2 < 8; x2++)
#pragma unroll
        for (int y = 0; y < 8; y++) acc2[x2][y] = 0ull;

    // K=64 in two 32-deep phases
    for (int kb = 0; kb < 64; kb += 32) {
#pragma unroll
        for (int s = 0; s < 8; s++) {
            int f4 = tid + s * 128;          // 0..1023 float4 per array
            int c  = f4 >> 5;                // k-row 0..31
            int g  = f4 & 31;                // float4 index within row
            *(float4*)&As[c][g * 4] =
                *(const float4*)&A[(kb + c) * LL + i0 + g * 4];
            int u = ((g & 1) << 4) + (g >> 1);   // interleave: lo/hi halves
            *(float4*)&Bs[c][u * 4] =
                *(const float4*)&B[(kb + c) * LL + j0 + g * 4];
        }
        __syncthreads();

#pragma unroll 8
        for (int k = 0; k < 32; k++) {
            __align__(16) unsigned long long a2[8];   // 16 rows as 8 pairs
            *(float4*)&a2[0] = *(float4*)&As[k][tx * 16];
            *(float4*)&a2[2] = *(float4*)&As[k][tx * 16 + 4];
            *(float4*)&a2[4] = *(float4*)&As[k][tx * 16 + 8];
            *(float4*)&a2[6] = *(float4*)&As[k][tx * 16 + 12];
            float b[8];                               // 8 cols, natural values
            *(float4*)&b[0] = *(float4*)&Bs[k][ty * 4];        // unit ty
            *(float4*)&b[4] = *(float4*)&Bs[k][64 + ty * 4];   // unit 16+ty
#pragma unroll
            for (int y = 0; y < 8; y++) {
                unsigned long long bb = bcast2(b[y]);
#pragma unroll
                for (int x2 = 0; x2 < 8; x2++)
                    ffma2(acc2[x2][y], a2[x2], bb);
            }
        }
        __syncthreads();
    }

    // Saliency validity masks (16 rows, 8 cols per thread)
    bool vr[16], vc[8];
#pragma unroll
    for (int x = 0; x < 16; x++) vr[x] = saV[i0 + tx * 16 + x] > 0.f;
#pragma unroll
    for (int y = 0; y < 8; y++)  vc[y] = saI[j0 + ty * 8 + y] > 0.f;

    // -------- column partial max (over this thread's 16 rows) --------
    float (*colsm)[128] = (float (*)[128])As;   // alias; safe after last sync
#pragma unroll
    for (int y = 0; y < 8; y++) {
        float m = NEGV;
#pragma unroll
        for (int x2 = 0; x2 < 8; x2++) {
            float2 f = *(float2*)&acc2[x2][y];
            float v0 = (vr[2 * x2]     && vc[y]) ? f.x * 0.15625f : NEGV;
            float v1 = (vr[2 * x2 + 1] && vc[y]) ? f.y * 0.15625f : NEGV;
            m = fmaxf(m, fmaxf(v0, v1));
        }
        colsm[tx][ty * 8 + y] = m;
    }

    // -------- row (max, first-argmax): local scan + shfl over 16 lanes ------
    // lane = (tx&1)*16 + ty, so the 16 ty lanes are contiguous 16-groups.
#pragma unroll
    for (int x2 = 0; x2 < 8; x2++) {
#pragma unroll
        for (int h = 0; h < 2; h++) {
            float v = NEGV;
            int   j = j0 + ty * 8;
#pragma unroll
            for (int y = 0; y < 8; y++) {
                float2 f = *(float2*)&acc2[x2][y];
                float raw = h ? f.y : f.x;
                float val = (vr[2 * x2 + h] && vc[y]) ? raw * 0.15625f : NEGV;
                if (val > v) { v = val; j = j0 + ty * 8 + y; }
            }
#pragma unroll
            for (int d = 1; d < 16; d <<= 1) {
                float ov = __shfl_xor_sync(0xffffffffu, v, d);
                int   oj = __shfl_xor_sync(0xffffffffu, j, d);
                if (ov > v || (ov == v && oj < j)) { v = ov; j = oj; }
            }
            if (ty == 0) {
                int i = i0 + tx * 16 + 2 * x2 + h;
                g_rowv[ct * LL + i] = v;     // transposed: coalesced readers
                g_rowj[ct * LL + i] = j;
            }
        }
    }

    __syncthreads();
    // finish column reduction across the 8 tx-groups (all 128 threads)
    {
        float m = colsm[0][tid];
#pragma unroll
        for (int t = 1; t < 8; t++) m = fmaxf(m, colsm[t][tid]);
        g_colp[rt * LL + j0 + tid] = m;      // transposed: coalesced
    }
}

// ---------------------------------------------------------------------------
// Kernel 2: column-partial reduce (blocks 0..24) + bilinear upsample
// 80x80 -> 640x640 align_corners (blocks 25..1624).
// ---------------------------------------------------------------------------
__global__ void colmax_upsample_kernel(const float* __restrict__ in,
                                       float* __restrict__ out)
{
    if (blockIdx.x < 25) {
        int j = blockIdx.x * 256 + threadIdx.x;
        float m = g_colp[j];
#pragma unroll 7
        for (int t = 1; t < NTILE; t++) m = fmaxf(m, g_colp[t * LL + j]);
        g_colmax[j] = m;
        return;
    }
    int o = (blockIdx.x - 25) * 256 + threadIdx.x;
    int oy = o / 640, ox = o % 640;
    const float step = 79.0f / 639.0f;
    float ysf = oy * step;
    float xsf = ox * step;
    int y0 = (int)ysf;
    int x0 = (int)xsf;
    int y1 = min(y0 + 1, WW - 1);
    int x1 = min(x0 + 1, WW - 1);
    float wy = ysf - (float)y0;
    float wx = xsf - (float)x0;
    float v00 = in[y0 * WW + x0], v01 = in[y0 * WW + x1];
    float v10 = in[y1 * WW + x0], v11 = in[y1 * WW + x1];
    float r0 = v00 * (1.f - wy) + v10 * wy;   // interp along H first (matches ref)
    float r1 = v01 * (1.f - wy) + v11 * wy;
    out[38400 + o] = r0 * (1.f - wx) + r1 * wx;
}

// ---------------------------------------------------------------------------
// Kernel 3: per-row finalize — mutual-NN test + outputs
// out layout (flattened tuple, float32):
//   [0      : 12800)  mkpts0  [L,2]
//   [12800  : 25600)  mkpts1  [1,L,2]
//   [25600  : 32000)  mask_v  [1,L]
//   [32000  : 38400)  score   [1,L]
//   [38400  : 448000) sa_ir_up [1,1,640,640]
// ---------------------------------------------------------------------------
__global__ void finalize_kernel(float* __restrict__ out)
{
    int i = blockIdx.x * 256 + threadIdx.x;
    if (i >= LL) return;

    float best = g_rowv[i];
    int   bj   = g_rowj[i];
#pragma unroll 7
    for (int t = 1; t < NTILE; t++) {
        float v = g_rowv[t * LL + i];
        if (v > best) { best = v; bj = g_rowj[t * LL + i]; }  // strict > keeps first
    }

    // mutual nearest neighbor: row max must also be its column's max, and > 0
    float mv = (best > 0.f && best == g_colmax[bj]) ? 1.f : 0.f;
    int   aj = (mv > 0.f) ? bj : 0;   // jnp.argmax of all-zero mask row -> 0

    out[2 * i]     = (float)((i % WW) * 8);
    out[2 * i + 1] = (float)((i / WW) * 8);
    out[12800 + 2 * i]     = (float)((aj % WW) * 8);
    out[12800 + 2 * i + 1] = (float)((aj / WW) * 8);
    out[25600 + i] = mv;
    out[32000 + i] = (mv > 0.f) ? best : 0.f;
}

// ---------------------------------------------------------------------------
extern "C" void kernel_launch(void* const* d_in, const int* in_sizes, int n_in,
                              void* d_out, int out_size)
{
    const float* A   = (const float*)d_in[0];   // feat_reg_vi [1,64,80,80]
    const float* B   = (const float*)d_in[1];   // feat_reg_ir [1,64,80,80]
    const float* saV = (const float*)d_in[2];   // feat_sa_vi  [1,1,80,80]
    const float* saI = (const float*)d_in[3];   // feat_sa_ir  [1,1,80,80]
    float* out = (float*)d_out;

    dim3 grid(NTILE, NTILE);
    conf_kernel<<<grid, 128>>>(A, B, saV, saI);
    colmax_upsample_kernel<<<1625, 256>>>(saI, out);
    finalize_kernel<<<25, 256>>>(out);
}